// round 1
// baseline (speedup 1.0000x reference)
#include <cuda_runtime.h>
#include <cstdint>
#include <math.h>

// Problem dims (fixed by the dataset)
#define NTOK   8192            // B*S = 4*2048
#define HD     1024
#define FD     4096
#define NE     8
#define NPAIR  (NTOK * 2)      // top-2

// ---------------- scratch (__device__ globals: allocation-rule safe) --------
__device__ int   g_count[NE];
__device__ int   g_list[NE][NTOK];          // pair ids (t*2+k) per expert
__device__ float g_pairw[NPAIR];            // gate prob per pair slot
__device__ float g_h[(size_t)NPAIR * FD];   // fp32 intermediate, 256 MiB

// ---------------- reset: zero output + counters (every replay!) -------------
__global__ void reset_kernel(float4* out4, int n4) {
    int i = blockIdx.x * blockDim.x + threadIdx.x;
    if (i < n4) out4[i] = make_float4(0.f, 0.f, 0.f, 0.f);
    if (i < NE) g_count[i] = 0;
}

// ---------------- gating: logits, softmax, top-2, build gather lists --------
__global__ void gate_kernel(const float* __restrict__ x,
                            const float* __restrict__ gw) {
    const int t = blockIdx.x;
    const int warp = threadIdx.x >> 5, lane = threadIdx.x & 31;
    __shared__ float logits[NE];
    const float* xr = x + (size_t)t * HD;
    const float* wr = gw + warp * HD;       // 8 warps = 8 experts
    float s = 0.f;
#pragma unroll 8
    for (int h = lane; h < HD; h += 32) s = fmaf(xr[h], wr[h], s);
#pragma unroll
    for (int o = 16; o > 0; o >>= 1) s += __shfl_xor_sync(0xffffffffu, s, o);
    if (lane == 0) logits[warp] = s;
    __syncthreads();
    if (threadIdx.x == 0) {
        float mx = logits[0];
        for (int e = 1; e < NE; e++) mx = fmaxf(mx, logits[e]);
        float pe[NE]; float den = 0.f;
        for (int e = 0; e < NE; e++) { pe[e] = expf(logits[e] - mx); den += pe[e]; }
        int i1 = 0;
        for (int e = 1; e < NE; e++) if (pe[e] > pe[i1]) i1 = e;  // lowest idx on tie
        int i2 = (i1 == 0) ? 1 : 0;
        for (int e = 0; e < NE; e++) if (e != i1 && pe[e] > pe[i2]) i2 = e;
        float inv = 1.f / den;
        int p0 = t * 2, p1 = t * 2 + 1;
        g_pairw[p0] = pe[i1] * inv;
        g_pairw[p1] = pe[i2] * inv;
        int k0 = atomicAdd(&g_count[i1], 1); g_list[i1][k0] = p0;
        int k1 = atomicAdd(&g_count[i2], 1); g_list[i2][k1] = p1;
    }
}

// ---------------- tf32 mma helpers ------------------------------------------
__device__ __forceinline__ uint32_t f2tf(float f) {
    uint32_t u;
    asm("cvt.rna.tf32.f32 %0, %1;" : "=r"(u) : "f"(f));
    return u;
}
__device__ __forceinline__ void mma_tf32(float c[4], const uint32_t a[4],
                                         const uint32_t b[2]) {
    asm volatile(
        "mma.sync.aligned.m16n8k8.row.col.f32.tf32.tf32.f32 "
        "{%0,%1,%2,%3},{%4,%5,%6,%7},{%8,%9},{%0,%1,%2,%3};\n"
        : "+f"(c[0]), "+f"(c[1]), "+f"(c[2]), "+f"(c[3])
        : "r"(a[0]), "r"(a[1]), "r"(a[2]), "r"(a[3]), "r"(b[0]), "r"(b[1]));
}
__device__ __forceinline__ void cp16(void* dst, const void* src) {
    uint32_t d = (uint32_t)__cvta_generic_to_shared(dst);
    asm volatile("cp.async.ca.shared.global [%0], [%1], 16;\n" :: "r"(d), "l"(src));
}

// ---------------- grouped gather-GEMM ---------------------------------------
// MODE 0: h[p] = silu(x[t] @ w1[e] + b1[e])     M=cnt K=HD  N=FD
// MODE 1: out[t] += pairw[p]*(h[p] @ w2[e] + b2[e])  M=cnt K=FD  N=HD
template <int MODE>
__global__ __launch_bounds__(256)
void moe_gemm(const float* __restrict__ x,
              const float* __restrict__ w1, const float* __restrict__ b1,
              const float* __restrict__ w2, const float* __restrict__ b2,
              float* __restrict__ out) {
    constexpr int BM = 128, BN = 128, BK = 16;
    constexpr int K = (MODE == 0) ? HD : FD;
    constexpr int N = (MODE == 0) ? FD : HD;
    const int e = blockIdx.z;
    const int cnt = g_count[e];
    const int rowBase = blockIdx.y * BM;
    if (rowBase >= cnt) return;                 // idle worst-case block
    const int n0 = blockIdx.x * BN;
    const float* __restrict__ Bmat =
        (MODE == 0) ? (w1 + (size_t)e * HD * FD) : (w2 + (size_t)e * FD * HD);
    const float* __restrict__ bias = (MODE == 0) ? (b1 + e * FD) : (b2 + e * HD);

    __shared__ __align__(16) float As[2][BM][BK + 4];   // bank-conflict-free
    __shared__ __align__(16) float Bs[2][BK][BN + 8];
    __shared__ int rowP[BM];
    __shared__ const float* rowSrc[BM];

    const int tid = threadIdx.x;
    if (tid < BM) {
        int gi = rowBase + tid;
        int pp = (gi < cnt) ? g_list[e][gi] : -1;
        rowP[tid] = pp;
        const float* s;
        if (MODE == 0) s = (pp >= 0) ? (x + (size_t)(pp >> 1) * HD) : x;
        else           s = (pp >= 0) ? (g_h + (size_t)pp * FD) : g_h;
        rowSrc[tid] = s;
    }
    __syncthreads();

    const int lane = tid & 31, warp = tid >> 5;
    const int wm = (warp & 1) * 64;            // 2x4 warp grid, 64x32 warp tile
    const int wn = (warp >> 1) * 32;
    const int grp = lane >> 2, quad = lane & 3;

    float acc[4][4][4];
#pragma unroll
    for (int a = 0; a < 4; a++)
#pragma unroll
        for (int b = 0; b < 4; b++)
#pragma unroll
            for (int c = 0; c < 4; c++) acc[a][b][c] = 0.f;

    auto loadTile = [&](int buf, int kt) {
        const int k0 = kt * BK;
#pragma unroll
        for (int c = 0; c < 2; ++c) {           // A: 512 16B chunks / 256 thr
            int id = tid + c * 256;
            int r = id >> 2, sg = id & 3;       // 4 chunks per row
            cp16(&As[buf][r][sg * 4], rowSrc[r] + k0 + sg * 4);
        }
#pragma unroll
        for (int c = 0; c < 2; ++c) {           // B: 512 16B chunks
            int id = tid + c * 256;
            int r = id >> 5, sg = id & 31;      // 32 chunks per row
            cp16(&Bs[buf][r][sg * 4], Bmat + (size_t)(k0 + r) * N + n0 + sg * 4);
        }
        asm volatile("cp.async.commit_group;\n");
    };

    constexpr int KT = K / BK;
    loadTile(0, 0);
    for (int kt = 0; kt < KT; ++kt) {
        if (kt + 1 < KT) {
            loadTile((kt + 1) & 1, kt + 1);
            asm volatile("cp.async.wait_group 1;\n");
        } else {
            asm volatile("cp.async.wait_group 0;\n");
        }
        __syncthreads();
        const int b = kt & 1;
#pragma unroll
        for (int ks = 0; ks < BK / 8; ++ks) {
            uint32_t af[4][4], bf[4][2];
#pragma unroll
            for (int mi = 0; mi < 4; ++mi) {
                int m0 = wm + mi * 16 + grp;
                af[mi][0] = f2tf(As[b][m0][ks * 8 + quad]);
                af[mi][1] = f2tf(As[b][m0 + 8][ks * 8 + quad]);
                af[mi][2] = f2tf(As[b][m0][ks * 8 + quad + 4]);
                af[mi][3] = f2tf(As[b][m0 + 8][ks * 8 + quad + 4]);
            }
#pragma unroll
            for (int ni = 0; ni < 4; ++ni) {
                int c0 = wn + ni * 8 + grp;
                bf[ni][0] = f2tf(Bs[b][ks * 8 + quad][c0]);
                bf[ni][1] = f2tf(Bs[b][ks * 8 + quad + 4][c0]);
            }
#pragma unroll
            for (int mi = 0; mi < 4; ++mi)
#pragma unroll
                for (int ni = 0; ni < 4; ++ni) mma_tf32(acc[mi][ni], af[mi], bf[ni]);
        }
        __syncthreads();
    }

    // epilogue
#pragma unroll
    for (int mi = 0; mi < 4; ++mi) {
#pragma unroll
        for (int half = 0; half < 2; ++half) {
            int li = wm + mi * 16 + grp + half * 8;
            if (rowBase + li >= cnt) continue;
            int pp = rowP[li];
            if (MODE == 0) {
                float* hrow = g_h + (size_t)pp * FD;
#pragma unroll
                for (int ni = 0; ni < 4; ++ni) {
                    int nc = n0 + wn + ni * 8 + 2 * quad;
                    float v0 = acc[mi][ni][half * 2 + 0] + bias[nc];
                    float v1 = acc[mi][ni][half * 2 + 1] + bias[nc + 1];
                    v0 = v0 / (1.f + expf(-v0));          // silu
                    v1 = v1 / (1.f + expf(-v1));
                    *reinterpret_cast<float2*>(&hrow[nc]) = make_float2(v0, v1);
                }
            } else {
                float wgt = g_pairw[pp];
                float* orow = out + (size_t)(pp >> 1) * HD;
#pragma unroll
                for (int ni = 0; ni < 4; ++ni) {
                    int nc = n0 + wn + ni * 8 + 2 * quad;
                    float v0 = acc[mi][ni][half * 2 + 0] + bias[nc];
                    float v1 = acc[mi][ni][half * 2 + 1] + bias[nc + 1];
                    atomicAdd(&orow[nc], wgt * v0);       // exactly 2 adds/elem:
                    atomicAdd(&orow[nc + 1], wgt * v1);   // commutative => determ.
                }
            }
        }
    }
}

// ---------------- launch -----------------------------------------------------
extern "C" void kernel_launch(void* const* d_in, const int* in_sizes, int n_in,
                              void* d_out, int out_size) {
    const float* x  = (const float*)d_in[0];   // [4,2048,1024]
    const float* gw = (const float*)d_in[1];   // [8,1024]
    const float* w1 = (const float*)d_in[2];   // [8,1024,4096]
    const float* b1 = (const float*)d_in[3];   // [8,4096]
    const float* w2 = (const float*)d_in[4];   // [8,4096,1024]
    const float* b2 = (const float*)d_in[5];   // [8,1024]
    float* out = (float*)d_out;                // [4,2048,1024] fp32

    int n4 = out_size / 4;
    reset_kernel<<<(n4 + 255) / 256, 256>>>((float4*)out, n4);
    gate_kernel<<<NTOK, 256>>>(x, gw);
    moe_gemm<0><<<dim3(FD / 128, NTOK / 128, NE), 256>>>(x, w1, b1, w2, b2, out);
    moe_gemm<1><<<dim3(HD / 128, NTOK / 128, NE), 256>>>(x, w1, b1, w2, b2, out);
}

// round 2
// speedup vs baseline: 2.0864x; 2.0864x over previous
#include <cuda_runtime.h>
#include <cuda_fp16.h>
#include <cstdint>
#include <math.h>

// Problem dims (fixed by the dataset)
#define NTOK   8192            // B*S = 4*2048
#define HD     1024
#define FD     4096
#define NE     8
#define NPAIR  (NTOK * 2)      // top-2

// ---------------- scratch (__device__ globals: allocation-rule safe) --------
__device__ int    g_count[NE];
__device__ int    g_list[NE][NTOK];           // pair ids (t*2+k) per expert
__device__ float  g_pairw[NPAIR];             // gate prob per pair slot
__device__ __half g_w1h[(size_t)NE * HD * FD];   // 67 MB
__device__ __half g_w2h[(size_t)NE * FD * HD];   // 67 MB
__device__ __half g_xh[(size_t)NTOK * HD];       // 16 MB
__device__ __half g_hh[(size_t)NPAIR * FD];      // 134 MB fp16 intermediate

// ---------------- fp32 -> fp16 convert (runs every replay; deterministic) ---
__global__ void cvt_f2h(const float4* __restrict__ s, int which, int n4) {
    int i = blockIdx.x * blockDim.x + threadIdx.x;
    if (i >= n4) return;
    __half2* dst = (which == 0) ? (__half2*)g_w1h
                 : (which == 1) ? (__half2*)g_w2h
                                : (__half2*)g_xh;
    float4 v = s[i];
    uint2 o;
    *reinterpret_cast<__half2*>(&o.x) = __floats2half2_rn(v.x, v.y);
    *reinterpret_cast<__half2*>(&o.y) = __floats2half2_rn(v.z, v.w);
    reinterpret_cast<uint2*>(dst)[i] = o;
}

// ---------------- reset: zero output + counters (every replay!) -------------
__global__ void reset_kernel(float4* out4, int n4) {
    int i = blockIdx.x * blockDim.x + threadIdx.x;
    if (i < n4) out4[i] = make_float4(0.f, 0.f, 0.f, 0.f);
    if (i < NE) g_count[i] = 0;
}

// ---------------- gating: logits, softmax, top-2, build gather lists --------
__global__ void gate_kernel(const float* __restrict__ x,
                            const float* __restrict__ gw) {
    const int t = blockIdx.x;
    const int warp = threadIdx.x >> 5, lane = threadIdx.x & 31;
    __shared__ float logits[NE];
    const float* xr = x + (size_t)t * HD;
    const float* wr = gw + warp * HD;       // 8 warps = 8 experts
    float s = 0.f;
#pragma unroll 8
    for (int h = lane; h < HD; h += 32) s = fmaf(xr[h], wr[h], s);
#pragma unroll
    for (int o = 16; o > 0; o >>= 1) s += __shfl_xor_sync(0xffffffffu, s, o);
    if (lane == 0) logits[warp] = s;
    __syncthreads();
    if (threadIdx.x == 0) {
        float mx = logits[0];
        for (int e = 1; e < NE; e++) mx = fmaxf(mx, logits[e]);
        float pe[NE]; float den = 0.f;
        for (int e = 0; e < NE; e++) { pe[e] = expf(logits[e] - mx); den += pe[e]; }
        int i1 = 0;
        for (int e = 1; e < NE; e++) if (pe[e] > pe[i1]) i1 = e;  // lowest idx on tie
        int i2 = (i1 == 0) ? 1 : 0;
        for (int e = 0; e < NE; e++) if (e != i1 && pe[e] > pe[i2]) i2 = e;
        float inv = 1.f / den;
        int p0 = t * 2, p1 = t * 2 + 1;
        g_pairw[p0] = pe[i1] * inv;
        g_pairw[p1] = pe[i2] * inv;
        int k0 = atomicAdd(&g_count[i1], 1); g_list[i1][k0] = p0;
        int k1 = atomicAdd(&g_count[i2], 1); g_list[i2][k1] = p1;
    }
}

// ---------------- mma / ldmatrix helpers ------------------------------------
__device__ __forceinline__ void mma_f16(float c[4], const uint32_t a[4],
                                        uint32_t b0, uint32_t b1) {
    asm volatile(
        "mma.sync.aligned.m16n8k16.row.col.f32.f16.f16.f32 "
        "{%0,%1,%2,%3},{%4,%5,%6,%7},{%8,%9},{%0,%1,%2,%3};\n"
        : "+f"(c[0]), "+f"(c[1]), "+f"(c[2]), "+f"(c[3])
        : "r"(a[0]), "r"(a[1]), "r"(a[2]), "r"(a[3]), "r"(b0), "r"(b1));
}
__device__ __forceinline__ void ldsm_x4(uint32_t r[4], uint32_t a) {
    asm volatile("ldmatrix.sync.aligned.m8n8.x4.shared.b16 {%0,%1,%2,%3},[%4];\n"
                 : "=r"(r[0]), "=r"(r[1]), "=r"(r[2]), "=r"(r[3]) : "r"(a));
}
__device__ __forceinline__ void ldsm_x4_t(uint32_t r[4], uint32_t a) {
    asm volatile("ldmatrix.sync.aligned.m8n8.x4.trans.shared.b16 {%0,%1,%2,%3},[%4];\n"
                 : "=r"(r[0]), "=r"(r[1]), "=r"(r[2]), "=r"(r[3]) : "r"(a));
}
__device__ __forceinline__ void cp16(void* dst, const void* src) {
    uint32_t d = (uint32_t)__cvta_generic_to_shared(dst);
    asm volatile("cp.async.ca.shared.global [%0], [%1], 16;\n" :: "r"(d), "l"(src));
}

// ---------------- grouped gather-GEMM (fp16 in, fp32 acc) -------------------
// MODE 0: g_hh[p] = silu(xh[t] @ w1h[e] + b1[e])        M=cnt K=HD  N=FD
// MODE 1: out[t] += pairw[p]*(g_hh[p] @ w2h[e] + b2[e]) M=cnt K=FD  N=HD
template <int MODE>
__global__ __launch_bounds__(256)
void moe_gemm(const float* __restrict__ b1g, const float* __restrict__ b2g,
              float* __restrict__ out) {
    constexpr int BM = 128, BN = 128, BK = 32;
    constexpr int K = (MODE == 0) ? HD : FD;
    constexpr int N = (MODE == 0) ? FD : HD;
    constexpr int AS = BK + 8;   // 40 halves, 80B row (16B aligned, conflict-free)
    constexpr int BS2 = BN + 8;  // 136 halves, 272B row
    const int e = blockIdx.z;
    const int cnt = g_count[e];
    const int rowBase = blockIdx.y * BM;
    if (rowBase >= cnt) return;                 // idle worst-case block
    const int n0 = blockIdx.x * BN;
    const __half* __restrict__ Bmat =
        (MODE == 0) ? (g_w1h + (size_t)e * HD * FD) : (g_w2h + (size_t)e * FD * HD);
    const float* __restrict__ bias = (MODE == 0) ? (b1g + e * FD) : (b2g + e * HD);

    __shared__ __align__(16) __half Asm[2][BM][AS];
    __shared__ __align__(16) __half Bsm[2][BK][BS2];
    __shared__ int rowP[BM];
    __shared__ const __half* rowSrc[BM];

    const int tid = threadIdx.x;
    if (tid < BM) {
        int gi = rowBase + tid;
        int pp = (gi < cnt) ? g_list[e][gi] : -1;
        rowP[tid] = pp;
        const __half* s;
        if (MODE == 0) s = (pp >= 0) ? (g_xh + (size_t)(pp >> 1) * HD) : g_xh;
        else           s = (pp >= 0) ? (g_hh + (size_t)pp * FD) : g_hh;
        rowSrc[tid] = s;
    }
    __syncthreads();

    const int lane = tid & 31, warp = tid >> 5;
    const int wm = (warp & 1) * 64;            // 2x4 warp grid, 64x32 warp tile
    const int wn = (warp >> 1) * 32;
    const int grp = lane >> 2, quad = lane & 3;

    const uint32_t aBase = (uint32_t)__cvta_generic_to_shared(&Asm[0][0][0]);
    const uint32_t bBase = (uint32_t)__cvta_generic_to_shared(&Bsm[0][0][0]);
    constexpr uint32_t aBufB = BM * AS * 2;     // bytes per A buffer
    constexpr uint32_t bBufB = BK * BS2 * 2;

    float acc[4][4][4];
#pragma unroll
    for (int a = 0; a < 4; a++)
#pragma unroll
        for (int b = 0; b < 4; b++)
#pragma unroll
            for (int c = 0; c < 4; c++) acc[a][b][c] = 0.f;

    auto loadTile = [&](int buf, int kt) {
        const int k0 = kt * BK;
#pragma unroll
        for (int c = 0; c < 2; ++c) {           // A: 512 16B chunks / 256 thr
            int id = tid + c * 256;
            int r = id >> 2, sg = id & 3;       // 4 chunks (64B) per row
            cp16(&Asm[buf][r][sg * 8], rowSrc[r] + k0 + sg * 8);
        }
#pragma unroll
        for (int c = 0; c < 2; ++c) {           // B: 512 16B chunks
            int id = tid + c * 256;
            int r = id >> 4, sg = id & 15;      // 16 chunks (256B) per row
            cp16(&Bsm[buf][r][sg * 8], Bmat + (size_t)(k0 + r) * N + n0 + sg * 8);
        }
        asm volatile("cp.async.commit_group;\n");
    };

    constexpr int KT = K / BK;
    loadTile(0, 0);
    for (int kt = 0; kt < KT; ++kt) {
        if (kt + 1 < KT) {
            loadTile((kt + 1) & 1, kt + 1);
            asm volatile("cp.async.wait_group 1;\n");
        } else {
            asm volatile("cp.async.wait_group 0;\n");
        }
        __syncthreads();
        const int buf = kt & 1;
        const uint32_t aB = aBase + buf * aBufB;
        const uint32_t bB = bBase + buf * bBufB;
#pragma unroll
        for (int ks = 0; ks < 2; ++ks) {        // two k16 steps per BK=32
            uint32_t af[4][4];
#pragma unroll
            for (int mi = 0; mi < 4; ++mi) {
                int row = wm + mi * 16 + (lane & 15);
                int col = ks * 16 + (lane >> 4) * 8;
                ldsm_x4(af[mi], aB + (row * AS + col) * 2);
            }
            uint32_t bf[2][4];
#pragma unroll
            for (int np = 0; np < 2; ++np) {
                int m = lane >> 3;
                int kk = ks * 16 + (m & 1) * 8 + (lane & 7);
                int nn = wn + np * 16 + (m >> 1) * 8;
                ldsm_x4_t(bf[np], bB + (kk * BS2 + nn) * 2);
            }
#pragma unroll
            for (int mi = 0; mi < 4; ++mi) {
#pragma unroll
                for (int np = 0; np < 2; ++np) {
                    mma_f16(acc[mi][np * 2 + 0], af[mi], bf[np][0], bf[np][1]);
                    mma_f16(acc[mi][np * 2 + 1], af[mi], bf[np][2], bf[np][3]);
                }
            }
        }
        __syncthreads();
    }

    // epilogue
#pragma unroll
    for (int mi = 0; mi < 4; ++mi) {
#pragma unroll
        for (int half = 0; half < 2; ++half) {
            int li = wm + mi * 16 + grp + half * 8;
            if (rowBase + li >= cnt) continue;
            int pp = rowP[li];
            if (MODE == 0) {
                __half* hrow = g_hh + (size_t)pp * FD;
#pragma unroll
                for (int ni = 0; ni < 4; ++ni) {
                    int nc = n0 + wn + ni * 8 + 2 * quad;
                    float v0 = acc[mi][ni][half * 2 + 0] + bias[nc];
                    float v1 = acc[mi][ni][half * 2 + 1] + bias[nc + 1];
                    v0 = v0 / (1.f + expf(-v0));          // silu
                    v1 = v1 / (1.f + expf(-v1));
                    *reinterpret_cast<__half2*>(&hrow[nc]) = __floats2half2_rn(v0, v1);
                }
            } else {
                float wgt = g_pairw[pp];
                float* orow = out + (size_t)(pp >> 1) * HD;
#pragma unroll
                for (int ni = 0; ni < 4; ++ni) {
                    int nc = n0 + wn + ni * 8 + 2 * quad;
                    float v0 = acc[mi][ni][half * 2 + 0] + bias[nc];
                    float v1 = acc[mi][ni][half * 2 + 1] + bias[nc + 1];
                    atomicAdd(&orow[nc], wgt * v0);       // exactly 2 adds/elem:
                    atomicAdd(&orow[nc + 1], wgt * v1);   // commutative => determ.
                }
            }
        }
    }
}

// ---------------- launch -----------------------------------------------------
extern "C" void kernel_launch(void* const* d_in, const int* in_sizes, int n_in,
                              void* d_out, int out_size) {
    const float* x  = (const float*)d_in[0];   // [4,2048,1024]
    const float* gw = (const float*)d_in[1];   // [8,1024]
    const float* w1 = (const float*)d_in[2];   // [8,1024,4096]
    const float* b1 = (const float*)d_in[3];   // [8,4096]
    const float* w2 = (const float*)d_in[4];   // [8,4096,1024]
    const float* b2 = (const float*)d_in[5];   // [8,1024]
    float* out = (float*)d_out;                // [4,2048,1024] fp32

    int n4 = out_size / 4;
    reset_kernel<<<(n4 + 255) / 256, 256>>>((float4*)out, n4);
    gate_kernel<<<NTOK, 256>>>(x, gw);

    const int wN4 = NE * HD * FD / 4;           // 8.39M float4s
    cvt_f2h<<<(wN4 + 255) / 256, 256>>>((const float4*)w1, 0, wN4);
    cvt_f2h<<<(wN4 + 255) / 256, 256>>>((const float4*)w2, 1, wN4);
    const int xN4 = NTOK * HD / 4;
    cvt_f2h<<<(xN4 + 255) / 256, 256>>>((const float4*)x, 2, xN4);

    moe_gemm<0><<<dim3(FD / 128, NTOK / 128, NE), 256>>>(b1, b2, out);
    moe_gemm<1><<<dim3(HD / 128, NTOK / 128, NE), 256>>>(b1, b2, out);
}